// round 8
// baseline (speedup 1.0000x reference)
#include <cuda_runtime.h>
#include <cuda_bf16.h>

#define BATCH 16384
#define DIM   4096
#define DIM4  (DIM / 4)          // 1024 float4 column-groups
#define THREADS 256
#define CBLK  (DIM4 / THREADS)   // 4 column blocks
#define RPT   8                  // rows per block
#define RBLK  (BATCH / RPT)      // 2048 row blocks -> 8192 total blocks
#define RUN   8                  // all loads front-batched

__device__ __forceinline__ float fast_ex2(float x) {
    float r; asm("ex2.approx.f32 %0, %1;" : "=f"(r) : "f"(x)); return r;
}
__device__ __forceinline__ float fast_rcp(float x) {
    float r; asm("rcp.approx.f32 %0, %1;" : "=f"(r) : "f"(x)); return r;
}

// Per-column state:
//   exp family  (silu/sigmoid/tanh): out = (u*x + c) * sigmoid(a*x) + d
//   relu family (relu/leaky):        out = max(u*x, x)      (u reused)
struct Col { float u, c, d, k; bool isExp; };

__device__ __forceinline__ Col make_col(int f) {
    const float L2E = 1.4426950408889634f;
    Col o;
    o.isExp = (f == 1) || (f == 3) || (f == 4);
    if (o.isExp) o.u = (f == 1) ? 1.0f : 0.0f;
    else         o.u = (f == 2) ? 0.01f : 0.0f;
    o.c = (f == 3) ? 1.0f : ((f == 4) ? 2.0f : 0.0f);
    o.d = (f == 4) ? -1.0f : 0.0f;
    o.k = (f == 4) ? -2.0f * L2E : -L2E;
    return o;
}

__device__ __forceinline__ float act(float x, const Col& q, float m) {
    float e  = fast_ex2(q.k * x);              // exp(-a*x)
    float s  = fast_rcp(1.0f + e);             // sigmoid(a*x)
    float eo = fmaf(fmaf(q.u, x, q.c), s, q.d);
    float ro = fmaxf(q.u * x, x);
    float r  = q.isExp ? eo : ro;
    return fminf(r, m);
}

__global__ void __launch_bounds__(THREADS)
random_activation_kernel(const float4* __restrict__ x,
                         const float4* __restrict__ max_out,   // [DIM4]
                         const int4*   __restrict__ func_id,   // [DIM4]
                         float4*       __restrict__ out) {
    int c  = blockIdx.x * THREADS + threadIdx.x;   // column-group
    int r0 = blockIdx.y * RPT;

    const float4* __restrict__ px = x   + (size_t)r0 * DIM4 + c;
    float4*       __restrict__ po = out + (size_t)r0 * DIM4 + c;

    // Front-batch ALL 8 streaming loads (max per-thread MLP), then the
    // L2-hot metadata loads — 10 requests in flight before any compute.
    float4 xv[RUN];
#pragma unroll
    for (int j = 0; j < RUN; j++)
        xv[j] = __ldcs(px + j * DIM4);             // LDG.128 [base+imm]

    int4   f = func_id[c];                          // L2-resident broadcast
    float4 m = max_out[c];

    Col qx = make_col(f.x);
    Col qy = make_col(f.y);
    Col qz = make_col(f.z);
    Col qw = make_col(f.w);

#pragma unroll
    for (int j = 0; j < RUN; j++) {
        float4 r;
        r.x = act(xv[j].x, qx, m.x);
        r.y = act(xv[j].y, qy, m.y);
        r.z = act(xv[j].z, qz, m.z);
        r.w = act(xv[j].w, qw, m.w);
        __stcs(po + j * DIM4, r);                  // STG.128 [base+imm]
    }
}

extern "C" void kernel_launch(void* const* d_in, const int* in_sizes, int n_in,
                              void* d_out, int out_size) {
    const float4* x  = (const float4*)d_in[0];
    const float4* mo = (const float4*)d_in[1];
    const int4*   fi = (const int4*)d_in[2];
    float4* out = (float4*)d_out;

    dim3 grid(CBLK, RBLK);   // (4, 2048) = 8192 blocks
    random_activation_kernel<<<grid, THREADS>>>(x, mo, fi, out);
}

// round 9
// speedup vs baseline: 1.0749x; 1.0749x over previous
#include <cuda_runtime.h>
#include <cuda_bf16.h>

#define BATCH 16384
#define DIM   4096
#define DIM4  (DIM / 4)          // 1024 float4 column-groups
#define THREADS 256
#define CBLK  (DIM4 / THREADS)   // 4 column blocks
#define RPT   8                  // rows per block
#define RBLK  (BATCH / RPT)      // 2048 row blocks -> 8192 total blocks
#define RUN   4                  // load batch depth (2 batches per block)

__device__ __forceinline__ float fast_ex2(float x) {
    float r; asm("ex2.approx.f32 %0, %1;" : "=f"(r) : "f"(x)); return r;
}
__device__ __forceinline__ float fast_rcp(float x) {
    float r; asm("rcp.approx.f32 %0, %1;" : "=f"(r) : "f"(x)); return r;
}

// Per-column state:
//   exp family  (silu/sigmoid/tanh): out = (u*x + c) * sigmoid(a*x) + d
//   relu family (relu/leaky):        out = max(u*x, x)      (u reused)
struct Col { float u, c, d, k; bool isExp; };

__device__ __forceinline__ Col make_col(int f) {
    const float L2E = 1.4426950408889634f;
    Col o;
    o.isExp = (f == 1) || (f == 3) || (f == 4);
    if (o.isExp) o.u = (f == 1) ? 1.0f : 0.0f;
    else         o.u = (f == 2) ? 0.01f : 0.0f;
    o.c = (f == 3) ? 1.0f : ((f == 4) ? 2.0f : 0.0f);
    o.d = (f == 4) ? -1.0f : 0.0f;
    o.k = (f == 4) ? -2.0f * L2E : -L2E;
    return o;
}

__device__ __forceinline__ float act(float x, const Col& q, float m) {
    float e  = fast_ex2(q.k * x);              // exp(-a*x)
    float s  = fast_rcp(1.0f + e);             // sigmoid(a*x)
    float eo = fmaf(fmaf(q.u, x, q.c), s, q.d);
    float ro = fmaxf(q.u * x, x);
    float r  = q.isExp ? eo : ro;
    return fminf(r, m);
}

__global__ void __launch_bounds__(THREADS)
random_activation_kernel(const float4* __restrict__ x,
                         const float4* __restrict__ max_out,   // [DIM4]
                         const int4*   __restrict__ func_id,   // [DIM4]
                         float4*       __restrict__ out) {
    int c  = blockIdx.x * THREADS + threadIdx.x;   // column-group
    int r0 = blockIdx.y * RPT;

    const float4* __restrict__ px = x   + (size_t)r0 * DIM4 + c;
    float4*       __restrict__ po = out + (size_t)r0 * DIM4 + c;

    // First 4-deep batch of streaming loads issued before metadata so the
    // critical path is pure DRAM latency.
    float4 xv[RUN];
#pragma unroll
    for (int j = 0; j < RUN; j++)
        xv[j] = __ldcs(px + j * DIM4);             // LDG.128 [base+imm]

    int4   f = func_id[c];                          // L2-resident broadcast
    float4 m = max_out[c];

    Col qx = make_col(f.x);
    Col qy = make_col(f.y);
    Col qz = make_col(f.z);
    Col qw = make_col(f.w);

#pragma unroll
    for (int j0 = 0; j0 < RPT; j0 += RUN) {
#pragma unroll
        for (int j = 0; j < RUN; j++) {
            float4 v = xv[j];
            // Prefetch next batch into the same buffer slot immediately
            // after consuming this one (keeps loads in flight, regs flat).
            if (j0 + RUN < RPT)
                xv[j] = __ldcs(px + (j0 + RUN + j) * DIM4);
            float4 r;
            r.x = act(v.x, qx, m.x);
            r.y = act(v.y, qy, m.y);
            r.z = act(v.z, qz, m.z);
            r.w = act(v.w, qw, m.w);
            __stcs(po + (j0 + j) * DIM4, r);       // STG.128 [base+imm]
        }
    }
}

extern "C" void kernel_launch(void* const* d_in, const int* in_sizes, int n_in,
                              void* d_out, int out_size) {
    const float4* x  = (const float4*)d_in[0];
    const float4* mo = (const float4*)d_in[1];
    const int4*   fi = (const int4*)d_in[2];
    float4* out = (float4*)d_out;

    dim3 grid(CBLK, RBLK);   // (4, 2048) = 8192 blocks
    random_activation_kernel<<<grid, THREADS>>>(x, mo, fi, out);
}